// round 15
// baseline (speedup 1.0000x reference)
#include <cuda_runtime.h>
#include <cstdint>

// Problem constants (fixed shapes from reference)
#define B_ROWS 16384
#define T_LEN  4096
#define WORDS  (T_LEN / 32)    // 128 mask words per row
#define CHUNKS (T_LEN / 128)   // 32 warp-chunks (128 elems each) per row
#define THREADS 256
#define GRID   1216            // 8 blocks x 152 SMs: one exact resident wave

// Spread 8 bits (positions 0..7) to positions 0,4,8,...,28.
__device__ __forceinline__ uint32_t spread4(uint32_t x)
{
    x &= 0xffu;
    x = (x | (x << 12)) & 0x000F000Fu;
    x = (x | (x << 6))  & 0x03030303u;
    x = (x | (x << 3))  & 0x11111111u;
    return x;
}

__global__ void __launch_bounds__(THREADS, 8)
yawning_adjust_kernel(const float* __restrict__ drowsiness,
                      const int* __restrict__ gesture,
                      float* __restrict__ out)
{
    __shared__ alignas(16) uint32_t sball[CHUNKS * 4];  // raw interleaved ballots
    __shared__ int sred[THREADS / 32];

    const int tid  = threadIdx.x;
    const int lane = tid & 31;
    const int warp = tid >> 5;               // 0..7

#pragma unroll 1
    for (int row = blockIdx.x; row < B_ROWS; row += GRID) {
        const int4* __restrict__ g4 = (const int4*)(gesture + (size_t)row * T_LEN);

        // ── Phase 1: wide streaming loads (identical to best kernel) ─────
        // Warp w covers chunks {w, 8+w, 16+w, 24+w}; lane l loads int4 at
        // element c*128 + l*4 (LDG.128, fully coalesced, evict-first).
        int4 g[4];
#pragma unroll
        for (int i = 0; i < 4; i++)
            g[i] = __ldcs(&g4[(i * 8 + warp) * 32 + lane]);

        // ── Phase 2: ballot packing; lane 0 stores 4 ballots as one STS.128
#pragma unroll
        for (int i = 0; i < 4; i++) {
            const int c = i * 8 + warp;
            const uint32_t b0 = __ballot_sync(0xffffffffu, g[i].x == 2);
            const uint32_t b1 = __ballot_sync(0xffffffffu, g[i].y == 2);
            const uint32_t b2 = __ballot_sync(0xffffffffu, g[i].z == 2);
            const uint32_t b3 = __ballot_sync(0xffffffffu, g[i].w == 2);
            if (lane == 0)
                *(uint4*)&sball[c * 4] = make_uint4(b0, b1, b2, b3);
        }
        __syncthreads();

        // ── Phase 3: per-word streak counting (threads 0..127) ───────────
        // Each thread de-interleaves its own mask word AND the next word
        // from the raw ballots (no cross-thread smem dependency). A streak
        // of length >= L exists iff some start (m[t] && !m[t-1]) has
        // m[t..t+L-1] all set; window <= 6 bits ahead, 1 bit behind.
        int packed = 0;   // hc | (lc << 16)
        if (tid < WORDS) {
            const int w = tid;
            uint32_t wcur = 0, wnxt = 0;
            {
                const int c = w >> 2, j = w & 3;
#pragma unroll
                for (int k = 0; k < 4; k++)
                    wcur |= spread4(sball[c * 4 + k] >> (8 * j)) << k;
            }
            if (w + 1 < WORDS) {
                const int c = (w + 1) >> 2, j = (w + 1) & 3;
#pragma unroll
                for (int k = 0; k < 4; k++)
                    wnxt |= spread4(sball[c * 4 + k] >> (8 * j)) << k;
            }
            uint32_t prevbit = 0;
            if (w > 0) {
                const int c = (w - 1) >> 2, j = (w - 1) & 3;
                // bit 31 of word w-1 = ballot 3, bit 8j+7
                prevbit = (sball[c * 4 + 3] >> (8 * j + 7)) & 1u;
            }

            const uint64_t ext = ((uint64_t)wnxt << 32) | (uint64_t)wcur;
            const uint32_t starts = wcur & ~((wcur << 1) | prevbit);
            const uint64_t r4 = ext & (ext >> 1) & (ext >> 2) & (ext >> 3);
            const uint64_t r7 = r4  & (ext >> 4) & (ext >> 5) & (ext >> 6);

            packed = __popc(starts & (uint32_t)r4)
                   | (__popc(starts & (uint32_t)r7) << 16);
        }

        // ── Phase 4: block reduction + epilogue ──────────────────────────
#pragma unroll
        for (int off = 16; off > 0; off >>= 1)
            packed += __shfl_down_sync(0xffffffffu, packed, off);
        if (lane == 0) sred[warp] = packed;
        __syncthreads();   // publishes sred; also gates sball reuse next iter

        if (tid == 0) {
            int tot = 0;
#pragma unroll
            for (int i = 0; i < THREADS / 32; i++) tot += sred[i];
            const int hc = tot & 0xffff;
            const int lc = tot >> 16;

            float hadj = (hc >= 2) ? 0.18f * expf(-0.5f * (float)(hc - 2)) : 0.0f;
            float ladj = (lc >= 3) ? 0.05f * expf(-0.5f * (float)(lc - 3)) : 0.0f;
            float adj = fminf(hadj + ladj, 0.35f);
            float r = drowsiness[row] + adj;
            out[row] = fminf(fmaxf(r, 0.0f), 1.0f);
        }
    }
}

extern "C" void kernel_launch(void* const* d_in, const int* in_sizes, int n_in,
                              void* d_out, int out_size)
{
    const float* drowsiness = (const float*)d_in[0];   // [B, 1] fp32
    const int*   gesture    = (const int*)d_in[1];     // [B, T, 1] int32
    float*       out        = (float*)d_out;           // [B, 1] fp32
    (void)in_sizes; (void)n_in; (void)out_size;

    yawning_adjust_kernel<<<GRID, THREADS>>>(drowsiness, gesture, out);
}